// round 12
// baseline (speedup 1.0000x reference)
#include <cuda_runtime.h>
#include <cstdint>
#include <cstddef>

#define T_STEPS 1024
#define BATCH   64
#define DDIM    128
#define HDIM    512
#define ALPHA   0.1f

#define CLUSTER 8
#define NTHR    512

// Per subgroup: activation buffer [k(640)][b(2)] = 1280 floats; ping-pong x2.
// Subgroup A (batches b0+0,b0+1) at 0; B (b0+2,b0+3) at 2560.
#define SUB_FLOATS   1280
#define SUBB_OFF     2560
#define MBAR_OFF     5120                 // float idx; 4 mbars: A0 A1 B0 B1
#define SMEM_BYTES   ((MBAR_OFF + 8) * 4)

#define TX_BYTES 3584                     // 7 peers x 512B per subgroup-buffer

// ---- packed fp32x2 helpers ----
__device__ __forceinline__ unsigned long long fma2(unsigned long long a,
                                                   unsigned long long b,
                                                   unsigned long long c) {
    unsigned long long d;
    asm("fma.rn.f32x2 %0, %1, %2, %3;" : "=l"(d) : "l"(a), "l"(b), "l"(c));
    return d;
}
__device__ __forceinline__ unsigned long long splat2(float x) {
    unsigned long long d;
    asm("mov.b64 %0, {%1, %1};" : "=l"(d) : "f"(x));
    return d;
}
__device__ __forceinline__ unsigned long long pack2(float lo, float hi) {
    unsigned long long d;
    asm("mov.b64 %0, {%1, %2};" : "=l"(d) : "f"(lo), "f"(hi));
    return d;
}
__device__ __forceinline__ float lo32(unsigned long long v) {
    return __uint_as_float((unsigned)(v & 0xFFFFFFFFull));
}
__device__ __forceinline__ float hi32(unsigned long long v) {
    return __uint_as_float((unsigned)(v >> 32));
}

// ---- cluster / mbarrier helpers ----
__device__ __forceinline__ unsigned mapa_u32(unsigned addr, unsigned rank) {
    unsigned d;
    asm("mapa.shared::cluster.u32 %0, %1, %2;" : "=r"(d) : "r"(addr), "r"(rank));
    return d;
}
__device__ __forceinline__ void mbar_init(unsigned addr, unsigned cnt) {
    asm volatile("mbarrier.init.shared.b64 [%0], %1;" :: "r"(addr), "r"(cnt) : "memory");
}
__device__ __forceinline__ void mbar_arrive_expect_tx(unsigned addr, unsigned bytes) {
    asm volatile("mbarrier.arrive.expect_tx.shared.b64 _, [%0], %1;"
                 :: "r"(addr), "r"(bytes) : "memory");
}
__device__ __forceinline__ void mbar_wait_parity(unsigned addr, unsigned parity) {
    unsigned done;
    asm volatile(
        "{\n\t.reg .pred p;\n\t"
        "mbarrier.try_wait.parity.acquire.cta.shared::cta.b64 p, [%1], %2;\n\t"
        "selp.b32 %0, 1, 0, p;\n\t}"
        : "=r"(done) : "r"(addr), "r"(parity) : "memory");
    if (!done) {
        asm volatile(
            "{\n\t.reg .pred P1;\n\t"
            "WAIT_LOOP_%=:\n\t"
            "mbarrier.try_wait.parity.acquire.cta.shared::cta.b64 P1, [%0], %1, 0x989680;\n\t"
            "@P1 bra.uni WAIT_DONE_%=;\n\t"
            "bra.uni WAIT_LOOP_%=;\n\t"
            "WAIT_DONE_%=:\n\t}"
            :: "r"(addr), "r"(parity) : "memory");
    }
}
__device__ __forceinline__ void bulk_dsmem(unsigned dst_cluster, unsigned src_cta,
                                           unsigned bytes, unsigned mbar_cluster) {
    asm volatile(
        "cp.async.bulk.shared::cluster.shared::cta.mbarrier::complete_tx::bytes "
        "[%0], [%1], %2, [%3];"
        :: "r"(dst_cluster), "r"(src_cta), "r"(bytes), "r"(mbar_cluster) : "memory");
}
__device__ __forceinline__ void fence_proxy_async_cta() {
    asm volatile("fence.proxy.async.shared::cta;" ::: "memory");
}
__device__ __forceinline__ void cluster_sync_() {
    asm volatile("barrier.cluster.arrive.aligned;" ::: "memory");
    asm volatile("barrier.cluster.wait.aligned;" ::: "memory");
}

__global__ void __launch_bounds__(NTHR, 1)
rnn_kernel(const float* __restrict__ input, const float* __restrict__ Win,
           const float* __restrict__ bin,   const float* __restrict__ Whid,
           const float* __restrict__ bhid,  float* __restrict__ out)
{
    extern __shared__ float sA[];   // A[2][640][2] | B[2][640][2] | mbar[4]

    const int tid  = threadIdx.x;
    const int lane = tid & 31;
    const int w    = tid >> 5;
    const int bx   = blockIdx.x;
    const int rank = bx & (CLUSTER - 1);
    const int cl   = bx >> 3;
    const int b0   = cl * 4;
    const int g0   = rank * 64;
    const int gbase = g0 + w * 4;

    // lane's output after the 8-value butterfly: bits{4,3} -> gl, bit2 -> bbl
    const int gl  = ((lane >> 4) & 1) * 2 + ((lane >> 3) & 1);
    const int bbl = (lane >> 2) & 1;
    const int hmine = gbase + gl;

    // ---- W into registers (ALPHA pre-folded), ROTATED BUFFER LAYOUT ----
    // Position p (chunks 2p,2p+1) holds slice of rank (rank+1+p)&7, p<7;
    // position 7 (chunks 14,15) holds OWN slice. Static register indices.
    unsigned long long wA[20], wB[20];
    #pragma unroll
    for (int j = 0; j < 16; ++j) {
        int p  = j >> 1;
        int rr = (p < 7) ? ((rank + 1 + p) & 7) : rank;
        int h  = rr * 64 + (j & 1) * 32 + lane;
        wA[j] = pack2(ALPHA * Whid[(gbase + 0) * HDIM + h],
                      ALPHA * Whid[(gbase + 1) * HDIM + h]);
        wB[j] = pack2(ALPHA * Whid[(gbase + 2) * HDIM + h],
                      ALPHA * Whid[(gbase + 3) * HDIM + h]);
    }
    #pragma unroll
    for (int j = 16; j < 20; ++j) {
        int k = (j - 16) * 32 + lane;
        wA[j] = pack2(ALPHA * Win[(gbase + 0) * DDIM + k],
                      ALPHA * Win[(gbase + 1) * DDIM + k]);
        wB[j] = pack2(ALPHA * Win[(gbase + 2) * DDIM + k],
                      ALPHA * Win[(gbase + 3) * DDIM + k]);
    }
    const float breg = ALPHA * (bhid[hmine] + bin[hmine]);
    float vregA = 0.0f, vregB = 0.0f;

    const unsigned smemBase = (unsigned)__cvta_generic_to_shared(sA);
    const unsigned mbarBase = smemBase + MBAR_OFF * 4;
    // mbar idx: 0=A buf0, 1=A buf1, 2=B buf0, 3=B buf1

    // x staging slot for this thread: sub = tid>>8, d = (tid&255)>>1, bl = tid&1
    const int xsub = tid >> 8;
    const int xdd  = (tid & 255) >> 1;
    const int xbl  = tid & 1;
    const int xbatch = b0 + xsub * 2 + xbl;

    // ---- init: zero everything, stage x(0) into both subs' buf0, arm mbars ----
    for (int i = tid; i < MBAR_OFF / 4; i += NTHR) {
        float4 z = {0.f, 0.f, 0.f, 0.f};
        ((float4*)sA)[i] = z;
    }
    __syncthreads();   // zeroing done before x staging
    sA[xsub * SUBB_OFF + (512 + xdd) * 2 + xbl] =
        input[(size_t)xbatch * DDIM + xdd];
    if (tid == 0) {
        #pragma unroll
        for (int m = 0; m < 4; ++m) {
            mbar_init(mbarBase + m * 8, 1);
            mbar_arrive_expect_tx(mbarBase + m * 8, TX_BYTES);
        }
    }
    __syncthreads();
    cluster_sync_();   // mbars live before any peer bulk-copy can land

    #define GEMM2(KIDX, KK)                                                    \
        {                                                                      \
            float2 a2 = *(const float2*)&aBuf[(KIDX) * 2];                     \
            unsigned long long s0 = splat2(a2.x), s1 = splat2(a2.y);           \
            acc0 = fma2(wA[KK], s0, acc0); acc1 = fma2(wB[KK], s0, acc1);      \
            acc2 = fma2(wA[KK], s1, acc2); acc3 = fma2(wB[KK], s1, acc3);      \
        }

    // Full phase for one subgroup (SUB: 0=A, 1=B). Phase counters passed by NAME.
    #define PHASE(SUB, VREG, MB0, PH0, PH1)                                    \
    {                                                                          \
        if (t > 0) {                                                           \
            unsigned mb = mbarBase + (unsigned)((MB0 + cur) * 8);              \
            mbar_wait_parity(mb, (unsigned)(cur ? PH1 : PH0));                 \
            if (cur) PH1 ^= 1; else PH0 ^= 1;                                  \
            if (tid == 0) mbar_arrive_expect_tx(mb, TX_BYTES);                 \
        }                                                                      \
        const float* aBuf = sA + SUB * SUBB_OFF + cur * SUB_FLOATS;            \
        unsigned long long acc0 = 0, acc1 = 0, acc2 = 0, acc3 = 0;             \
        _Pragma("unroll")                                                      \
        for (int j = 0; j < 16; ++j)                                           \
            GEMM2(j * 32 + lane, j)                                            \
        _Pragma("unroll")                                                      \
        for (int j = 16; j < 20; ++j)                                          \
            GEMM2(512 + (j - 16) * 32 + lane, j)                               \
        /* 8-value butterfly over 32 lanes */                                  \
        float v0 = lo32(acc0), v1 = lo32(acc2), v2 = hi32(acc0),               \
              v3 = hi32(acc2), v4 = lo32(acc1), v5 = lo32(acc3),               \
              v6 = hi32(acc1), v7 = hi32(acc3);                                \
        {                                                                      \
            bool up = (lane & 16) != 0;                                        \
            float k0 = up ? v4 : v0, s0 = up ? v0 : v4;                        \
            float k1 = up ? v5 : v1, s1 = up ? v1 : v5;                        \
            float k2 = up ? v6 : v2, s2 = up ? v2 : v6;                        \
            float k3 = up ? v7 : v3, s3 = up ? v3 : v7;                        \
            v0 = k0 + __shfl_xor_sync(0xFFFFFFFFu, s0, 16);                    \
            v1 = k1 + __shfl_xor_sync(0xFFFFFFFFu, s1, 16);                    \
            v2 = k2 + __shfl_xor_sync(0xFFFFFFFFu, s2, 16);                    \
            v3 = k3 + __shfl_xor_sync(0xFFFFFFFFu, s3, 16);                    \
        }                                                                      \
        {                                                                      \
            bool up = (lane & 8) != 0;                                         \
            float k0 = up ? v2 : v0, s0 = up ? v0 : v2;                        \
            float k1 = up ? v3 : v1, s1 = up ? v1 : v3;                        \
            v0 = k0 + __shfl_xor_sync(0xFFFFFFFFu, s0, 8);                     \
            v1 = k1 + __shfl_xor_sync(0xFFFFFFFFu, s1, 8);                     \
        }                                                                      \
        {                                                                      \
            bool up = (lane & 4) != 0;                                         \
            float k0 = up ? v1 : v0, s0 = up ? v0 : v1;                        \
            v0 = k0 + __shfl_xor_sync(0xFFFFFFFFu, s0, 4);                     \
        }                                                                      \
        v0 += __shfl_xor_sync(0xFFFFFFFFu, v0, 2);                             \
        v0 += __shfl_xor_sync(0xFFFFFFFFu, v0, 1);                             \
        /* leaky update + relu (redundant across lane bits 0,1) */             \
        VREG = (1.0f - ALPHA) * VREG + (v0 + breg);                            \
        float fr = fmaxf(VREG, 0.f);                                           \
        if ((lane & 3) == 0)                                                   \
            out[((size_t)t * BATCH + b0 + SUB * 2 + bbl) * HDIM + hmine] = fr; \
        if (t + 1 < T_STEPS) {                                                 \
            const int nxt = cur ^ 1;                                           \
            float* nbuf = sA + SUB * SUBB_OFF + nxt * SUB_FLOATS;              \
            float frp = __shfl_xor_sync(0xFFFFFFFFu, fr, 4);  /* partner b */  \
            if ((lane & 7) == 0) {    /* lanes 0,8,16,24: bbl==0 owners */     \
                int lg = w * 4 + gl;                                           \
                *(float2*)&nbuf[(448 + lg) * 2] = make_float2(fr, frp);        \
            }                                                                  \
            if (xsub == SUB)          /* stage x(t+1) for own subgroup */      \
                nbuf[(512 + xdd) * 2 + xbl] = xv;                              \
            __syncthreads();                                                   \
            if (tid < 7) {                                                     \
                fence_proxy_async_cta();                                       \
                unsigned c = (unsigned)tid + ((tid >= rank) ? 1u : 0u);        \
                unsigned p = (unsigned)(rank - (int)c - 1) & 7u;               \
                unsigned src = smemBase                                        \
                    + (unsigned)((SUB * SUBB_OFF + nxt * SUB_FLOATS + 896) * 4);\
                unsigned dst = smemBase                                        \
                    + (unsigned)((SUB * SUBB_OFF + nxt * SUB_FLOATS            \
                                  + (int)p * 128) * 4);                        \
                unsigned mOff = mbarBase + (unsigned)((MB0 + nxt) * 8);        \
                bulk_dsmem(mapa_u32(dst, c), src, 512, mapa_u32(mOff, c));     \
            }                                                                  \
        }                                                                      \
    }

    int phA0 = 0, phA1 = 0, phB0 = 0, phB1 = 0;
    int cur = 0;
    for (int t = 0; t < T_STEPS; ++t) {
        // per-thread x(t+1) load — hidden under the two GEMMs
        float xv = 0.f;
        if (t + 1 < T_STEPS)
            xv = input[((size_t)(t + 1) * BATCH + xbatch) * DDIM + xdd];

        PHASE(0, vregA, 0, phA0, phA1)   // A: wait, GEMM, update, push A(t+1)
        PHASE(1, vregB, 2, phB0, phB1)   // B: its exchange flew during phase A

        cur ^= 1;
    }
}

extern "C" void kernel_launch(void* const* d_in, const int* in_sizes, int n_in,
                              void* d_out, int out_size)
{
    const float* input = (const float*)d_in[0];
    const float* Win   = (const float*)d_in[1];
    const float* bin   = (const float*)d_in[2];
    const float* Whid  = (const float*)d_in[3];
    const float* bhid  = (const float*)d_in[4];
    float* out = (float*)d_out;

    cudaFuncSetAttribute(rnn_kernel,
                         cudaFuncAttributeMaxDynamicSharedMemorySize, SMEM_BYTES);

    cudaLaunchConfig_t cfg = {};
    cfg.gridDim  = dim3(16 * CLUSTER, 1, 1);
    cfg.blockDim = dim3(NTHR, 1, 1);
    cfg.dynamicSmemBytes = SMEM_BYTES;
    cfg.stream = 0;

    cudaLaunchAttribute attr[1];
    attr[0].id = cudaLaunchAttributeClusterDimension;
    attr[0].val.clusterDim.x = CLUSTER;
    attr[0].val.clusterDim.y = 1;
    attr[0].val.clusterDim.z = 1;
    cfg.attrs = attr;
    cfg.numAttrs = 1;

    cudaLaunchKernelEx(&cfg, rnn_kernel, input, Win, bin, Whid, bhid, out);
}

// round 13
// speedup vs baseline: 1.1764x; 1.1764x over previous
#include <cuda_runtime.h>
#include <cstdint>
#include <cstddef>

#define T_STEPS 1024
#define BATCH   64
#define DDIM    128
#define HDIM    512
#define ALPHA   0.1f

#define CLUSTER 8
#define BPC     4
#define NTHR    512

#define ABUF_FLOATS  2560                 // [k(640)][b(4)] ; k<512 fr (8 rotated
                                          // 64-g positions), k>=512 x
#define SA_FLOATS    (2 * ABUF_FLOATS)    // ping-pong
#define MBAR_OFF     SA_FLOATS            // float idx; 2 mbars (buf0, buf1)
#define SMEM_BYTES   ((MBAR_OFF + 8) * 4)

#define TX_BYTES 7168                     // 7 peers x 1KB

// ---- packed fp32x2 helpers ----
__device__ __forceinline__ unsigned long long fma2(unsigned long long a,
                                                   unsigned long long b,
                                                   unsigned long long c) {
    unsigned long long d;
    asm("fma.rn.f32x2 %0, %1, %2, %3;" : "=l"(d) : "l"(a), "l"(b), "l"(c));
    return d;
}
__device__ __forceinline__ unsigned long long splat2(float x) {
    unsigned long long d;
    asm("mov.b64 %0, {%1, %1};" : "=l"(d) : "f"(x));
    return d;
}
__device__ __forceinline__ unsigned long long pack2(float lo, float hi) {
    unsigned long long d;
    asm("mov.b64 %0, {%1, %2};" : "=l"(d) : "f"(lo), "f"(hi));
    return d;
}
__device__ __forceinline__ float lo32(unsigned long long v) {
    return __uint_as_float((unsigned)(v & 0xFFFFFFFFull));
}
__device__ __forceinline__ float hi32(unsigned long long v) {
    return __uint_as_float((unsigned)(v >> 32));
}

// ---- cluster / mbarrier helpers ----
__device__ __forceinline__ unsigned mapa_u32(unsigned addr, unsigned rank) {
    unsigned d;
    asm("mapa.shared::cluster.u32 %0, %1, %2;" : "=r"(d) : "r"(addr), "r"(rank));
    return d;
}
__device__ __forceinline__ void mbar_init(unsigned addr, unsigned cnt) {
    asm volatile("mbarrier.init.shared.b64 [%0], %1;" :: "r"(addr), "r"(cnt) : "memory");
}
__device__ __forceinline__ void mbar_arrive_expect_tx(unsigned addr, unsigned bytes) {
    asm volatile("mbarrier.arrive.expect_tx.shared.b64 _, [%0], %1;"
                 :: "r"(addr), "r"(bytes) : "memory");
}
__device__ __forceinline__ void mbar_wait_parity(unsigned addr, unsigned parity) {
    unsigned done;
    asm volatile(
        "{\n\t.reg .pred p;\n\t"
        "mbarrier.try_wait.parity.acquire.cta.shared::cta.b64 p, [%1], %2;\n\t"
        "selp.b32 %0, 1, 0, p;\n\t}"
        : "=r"(done) : "r"(addr), "r"(parity) : "memory");
    if (!done) {
        asm volatile(
            "{\n\t.reg .pred P1;\n\t"
            "WAIT_LOOP_%=:\n\t"
            "mbarrier.try_wait.parity.acquire.cta.shared::cta.b64 P1, [%0], %1, 0x989680;\n\t"
            "@P1 bra.uni WAIT_DONE_%=;\n\t"
            "bra.uni WAIT_LOOP_%=;\n\t"
            "WAIT_DONE_%=:\n\t}"
            :: "r"(addr), "r"(parity) : "memory");
    }
}
__device__ __forceinline__ void bulk_dsmem(unsigned dst_cluster, unsigned src_cta,
                                           unsigned bytes, unsigned mbar_cluster) {
    asm volatile(
        "cp.async.bulk.shared::cluster.shared::cta.mbarrier::complete_tx::bytes "
        "[%0], [%1], %2, [%3];"
        :: "r"(dst_cluster), "r"(src_cta), "r"(bytes), "r"(mbar_cluster) : "memory");
}
__device__ __forceinline__ void fence_proxy_async_cta() {
    asm volatile("fence.proxy.async.shared::cta;" ::: "memory");
}
__device__ __forceinline__ void cluster_sync_() {
    asm volatile("barrier.cluster.arrive.aligned;" ::: "memory");
    asm volatile("barrier.cluster.wait.aligned;" ::: "memory");
}

__global__ void __launch_bounds__(NTHR, 1)
rnn_kernel(const float* __restrict__ input, const float* __restrict__ Win,
           const float* __restrict__ bin,   const float* __restrict__ Whid,
           const float* __restrict__ bhid,  float* __restrict__ out)
{
    extern __shared__ float sA[];   // [2][640][4] | mbar[2]

    const int tid  = threadIdx.x;
    const int lane = tid & 31;
    const int w    = tid >> 5;
    const int bx   = blockIdx.x;
    const int rank = bx & (CLUSTER - 1);
    const int cl   = bx >> 3;
    const int b0   = cl * BPC;
    const int g0   = rank * 64;
    const int gbase = g0 + w * 4;

    // lane's output after the butterfly (verified mapping):
    const int vidx = ((lane >> 4) & 1) * 8 + ((lane >> 3) & 1) * 4
                   + ((lane >> 2) & 1) * 2 + ((lane >> 1) & 1);
    const int gl = vidx >> 2;
    const int bb = vidx & 3;
    const int hmine = gbase + gl;

    // ---- W into registers (ALPHA pre-folded), ROTATED BUFFER LAYOUT ----
    // Position p (chunks 2p,2p+1) holds slice of rank (rank+1+p)&7, p<7;
    // position 7 (chunks 14,15) holds OWN slice. Static register indices.
    unsigned long long wA[20], wB[20];
    #pragma unroll
    for (int j = 0; j < 16; ++j) {
        int p  = j >> 1;
        int rr = (p < 7) ? ((rank + 1 + p) & 7) : rank;
        int h  = rr * 64 + (j & 1) * 32 + lane;
        wA[j] = pack2(ALPHA * Whid[(gbase + 0) * HDIM + h],
                      ALPHA * Whid[(gbase + 1) * HDIM + h]);
        wB[j] = pack2(ALPHA * Whid[(gbase + 2) * HDIM + h],
                      ALPHA * Whid[(gbase + 3) * HDIM + h]);
    }
    #pragma unroll
    for (int j = 16; j < 20; ++j) {
        int k = (j - 16) * 32 + lane;
        wA[j] = pack2(ALPHA * Win[(gbase + 0) * DDIM + k],
                      ALPHA * Win[(gbase + 1) * DDIM + k]);
        wB[j] = pack2(ALPHA * Win[(gbase + 2) * DDIM + k],
                      ALPHA * Win[(gbase + 3) * DDIM + k]);
    }
    const float breg = ALPHA * (bhid[hmine] + bin[hmine]);
    float vreg = 0.0f;

    const unsigned smemBase = (unsigned)__cvta_generic_to_shared(sA);
    const unsigned mbarBase = smemBase + MBAR_OFF * 4;

    // ---- per-pushing-warp peer base (hoisted mapa): warps 0..6, lane 0 ----
    // peer c's SMEM window base; mbars live in the same window.
    unsigned peerBase = 0;
    unsigned dstOff0  = 0;   // byte offset of my slice in peer's buffer (pos p)
    if (lane == 0 && w < 7) {
        unsigned c = (unsigned)w + ((w >= rank) ? 1u : 0u);
        unsigned p = (unsigned)(rank - (int)c - 1) & 7u;
        peerBase = mapa_u32(smemBase, c);
        dstOff0  = p * 256u * 4u;
    }

    // ---- init: buffer0 fr = 0 ; x = input[t=0]; arm both mbars ----
    {
        float4 z = {0.f, 0.f, 0.f, 0.f};
        ((float4*)sA)[tid] = z;
        int d = w * 8 + (lane >> 2);
        int b = lane & 3;
        sA[(HDIM + d) * 4 + b] = input[(size_t)(b0 + b) * DDIM + d];
    }
    if (tid == 0) {
        mbar_init(mbarBase + 0, 1);
        mbar_init(mbarBase + 8, 1);
        mbar_arrive_expect_tx(mbarBase + 0, TX_BYTES);
        mbar_arrive_expect_tx(mbarBase + 8, TX_BYTES);
    }
    __syncthreads();
    cluster_sync_();   // mbars live before any peer bulk-copy can land

    const int xd = w * 8 + (lane >> 2);
    const int xb = lane & 3;

    #define GEMM_STEP(KIDX, KK)                                                \
        {                                                                      \
            float4 a4 = *(const float4*)&aBuf[(KIDX) * 4];                     \
            unsigned long long s0 = splat2(a4.x), s1 = splat2(a4.y);           \
            unsigned long long s2 = splat2(a4.z), s3 = splat2(a4.w);           \
            acc[0] = fma2(wA[KK], s0, acc[0]); acc[1] = fma2(wB[KK], s0, acc[1]);\
            acc[2] = fma2(wA[KK], s1, acc[2]); acc[3] = fma2(wB[KK], s1, acc[3]);\
            acc[4] = fma2(wA[KK], s2, acc[4]); acc[5] = fma2(wB[KK], s2, acc[5]);\
            acc[6] = fma2(wA[KK], s3, acc[6]); acc[7] = fma2(wB[KK], s3, acc[7]);\
        }

    // ---- prologue: own chunks (zeros) + x chunks, on buffer 0 ----
    unsigned long long acc[8];
    #pragma unroll
    for (int i = 0; i < 8; ++i) acc[i] = 0ull;
    {
        const float* aBuf = sA;
        GEMM_STEP(14 * 32 + lane, 14)
        GEMM_STEP(15 * 32 + lane, 15)
        #pragma unroll
        for (int j = 16; j < 20; ++j)
            GEMM_STEP(HDIM + (j - 16) * 32 + lane, j)
    }

    int ph0 = 0, ph1 = 0;
    int cur = 0;
    for (int t = 0; t < T_STEPS; ++t) {
        // ---- wait for 7 peers' fr(t); re-arm for t+2 ----
        if (t > 0) {
            unsigned mb = mbarBase + (unsigned)(cur * 8);
            unsigned par = (unsigned)(cur ? ph1 : ph0);
            mbar_wait_parity(mb, par);
            if (cur) ph1 ^= 1; else ph0 ^= 1;
            if (tid == 0) mbar_arrive_expect_tx(mb, TX_BYTES);
        }

        // prefetch x(t+1) — hidden under the main GEMM
        float xv = 0.f;
        if (t + 1 < T_STEPS)
            xv = input[((size_t)(t + 1) * BATCH + b0 + xb) * DDIM + xd];

        const float* aBuf = sA + cur * ABUF_FLOATS;

        // ---- main GEMM: peer chunks 0..13, all-static addressing ----
        #pragma unroll
        for (int j = 0; j < 14; ++j)
            GEMM_STEP(j * 32 + lane, j)

        // ---- unpack + warp butterfly (16 outputs over 32 lanes) ----
        float v[16];
        #pragma unroll
        for (int b = 0; b < 4; ++b) {
            v[0 * 4 + b] = lo32(acc[2 * b]);
            v[1 * 4 + b] = hi32(acc[2 * b]);
            v[2 * 4 + b] = lo32(acc[2 * b + 1]);
            v[3 * 4 + b] = hi32(acc[2 * b + 1]);
        }
        #pragma unroll
        for (int s = 16, cnt = 16; s >= 2; s >>= 1, cnt >>= 1) {
            const bool up = (lane & s) != 0;
            const int half = cnt >> 1;
            #pragma unroll
            for (int i = 0; i < 8; ++i) {
                if (i >= half) break;
                float keep = up ? v[i + half] : v[i];
                float send = up ? v[i] : v[i + half];
                float got  = __shfl_xor_sync(0xFFFFFFFFu, send, s);
                v[i] = keep + got;
            }
        }
        v[0] += __shfl_xor_sync(0xFFFFFFFFu, v[0], 1);

        // ---- leaky update + relu ----
        vreg = (1.0f - ALPHA) * vreg + (v[0] + breg);
        float fr = fmaxf(vreg, 0.f);

        if (t + 1 < T_STEPS) {
            const int nxt = cur ^ 1;
            float* nbuf = sA + nxt * ABUF_FLOATS;

            // gather 4 batch values per g; write own POSITION-7 slice
            float frb1 = __shfl_xor_sync(0xFFFFFFFFu, fr, 2);
            unsigned long long p01 = pack2(fr, frb1);
            unsigned long long p23 = __shfl_xor_sync(0xFFFFFFFFu, p01, 4);
            if ((lane & 7) == 0) {
                int lg = w * 4 + (lane >> 3);      // local g 0..63
                *(float4*)&nbuf[(448 + lg) * 4] =
                    make_float4(lo32(p01), hi32(p01), lo32(p23), hi32(p23));
            }
            // stage x(t+1)
            nbuf[(HDIM + xd) * 4 + xb] = xv;

            __syncthreads();   // own pos-7 slice + x visible CTA-wide

            // ---- 7 WARPS push the contiguous 1KB own-slice to 7 peers ----
            // (hoisted mapa; addresses are peerBase + constants)
            if (lane == 0 && w < 7) {
                fence_proxy_async_cta();
                unsigned bufOff = (unsigned)(nxt * ABUF_FLOATS * 4);
                unsigned src = smemBase + bufOff + 448u * 16u;
                unsigned dst = peerBase + bufOff + dstOff0;
                unsigned mb  = peerBase + (unsigned)(MBAR_OFF * 4 + nxt * 8);
                bulk_dsmem(dst, src, 1024, mb);
            }

            // out STG moved off the peer-critical path (after push issue)
            if ((lane & 1) == 0)
                out[((size_t)t * BATCH + b0 + bb) * HDIM + hmine] = fr;

            // ---- prewait GEMM for t+1: own chunks 14,15 + x 16..19 ----
            #pragma unroll
            for (int i = 0; i < 8; ++i) acc[i] = 0ull;
            {
                const float* aBuf = nbuf;
                GEMM_STEP(14 * 32 + lane, 14)
                GEMM_STEP(15 * 32 + lane, 15)
                #pragma unroll
                for (int j = 16; j < 20; ++j)
                    GEMM_STEP(HDIM + (j - 16) * 32 + lane, j)
            }
        } else {
            if ((lane & 1) == 0)
                out[((size_t)t * BATCH + b0 + bb) * HDIM + hmine] = fr;
        }
        cur ^= 1;
    }
}

extern "C" void kernel_launch(void* const* d_in, const int* in_sizes, int n_in,
                              void* d_out, int out_size)
{
    const float* input = (const float*)d_in[0];
    const float* Win   = (const float*)d_in[1];
    const float* bin   = (const float*)d_in[2];
    const float* Whid  = (const float*)d_in[3];
    const float* bhid  = (const float*)d_in[4];
    float* out = (float*)d_out;

    cudaFuncSetAttribute(rnn_kernel,
                         cudaFuncAttributeMaxDynamicSharedMemorySize, SMEM_BYTES);

    cudaLaunchConfig_t cfg = {};
    cfg.gridDim  = dim3(16 * CLUSTER, 1, 1);
    cfg.blockDim = dim3(NTHR, 1, 1);
    cfg.dynamicSmemBytes = SMEM_BYTES;
    cfg.stream = 0;

    cudaLaunchAttribute attr[1];
    attr[0].id = cudaLaunchAttributeClusterDimension;
    attr[0].val.clusterDim.x = CLUSTER;
    attr[0].val.clusterDim.y = 1;
    attr[0].val.clusterDim.z = 1;
    cfg.attrs = attr;
    cfg.numAttrs = 1;

    cudaLaunchKernelEx(&cfg, rnn_kernel, input, Win, bin, Whid, bhid, out);
}

// round 17
// speedup vs baseline: 1.6708x; 1.4203x over previous
#include <cuda_runtime.h>
#include <cuda_bf16.h>
#include <cstdint>
#include <cstddef>

#define T_STEPS 1024
#define BATCH   64
#define DDIM    128
#define HDIM    512
#define ALPHA   0.1f
#define CLUSTER 8
#define NTHR    256

// SMEM: B ping-pong (2 x 10KB) | scratch 1KB | 2 mbars
// B layout (u32 units): [kblock(10)][jq(2)][n(8)][t0(4)][jlo(4)]
//   element (kblock,jq,n,t0,jlo) = bf16 pair {act[n][k], act[n][k+1]},
//   k = kblock*64 + ksl*16 + half*8 + 2*t0, where jlo_global = jq*4+jlo,
//   ksl = jlo_global>>1, half = jlo_global&1.
//   kblock r (r<8) = fr slice of rank r (1KB contiguous); kblocks 8,9 = x.
//   n: 0-3 = hi(batch b=n), 4-7 = lo(batch b=n-4).
#define BBUF_BYTES  10240
#define SCR_OFF     20480
#define MB_OFF      21504
#define SMEM_BYTES  21520
#define TX_BYTES    7168

// ---- cluster / mbarrier helpers (champion protocol) ----
__device__ __forceinline__ unsigned mapa_u32(unsigned addr, unsigned rank) {
    unsigned d;
    asm("mapa.shared::cluster.u32 %0, %1, %2;" : "=r"(d) : "r"(addr), "r"(rank));
    return d;
}
__device__ __forceinline__ void mbar_init(unsigned addr, unsigned cnt) {
    asm volatile("mbarrier.init.shared.b64 [%0], %1;" :: "r"(addr), "r"(cnt) : "memory");
}
__device__ __forceinline__ void mbar_arrive_expect_tx(unsigned addr, unsigned bytes) {
    asm volatile("mbarrier.arrive.expect_tx.shared.b64 _, [%0], %1;"
                 :: "r"(addr), "r"(bytes) : "memory");
}
__device__ __forceinline__ void mbar_wait_parity(unsigned addr, unsigned parity) {
    unsigned done;
    asm volatile(
        "{\n\t.reg .pred p;\n\t"
        "mbarrier.try_wait.parity.acquire.cta.shared::cta.b64 p, [%1], %2;\n\t"
        "selp.b32 %0, 1, 0, p;\n\t}"
        : "=r"(done) : "r"(addr), "r"(parity) : "memory");
    if (!done) {
        asm volatile(
            "{\n\t.reg .pred P1;\n\t"
            "WAIT_LOOP_%=:\n\t"
            "mbarrier.try_wait.parity.acquire.cta.shared::cta.b64 P1, [%0], %1, 0x989680;\n\t"
            "@P1 bra.uni WAIT_DONE_%=;\n\t"
            "bra.uni WAIT_LOOP_%=;\n\t"
            "WAIT_DONE_%=:\n\t}"
            :: "r"(addr), "r"(parity) : "memory");
    }
}
__device__ __forceinline__ void bulk_dsmem(unsigned dst, unsigned src,
                                           unsigned bytes, unsigned mb) {
    asm volatile(
        "cp.async.bulk.shared::cluster.shared::cta.mbarrier::complete_tx::bytes "
        "[%0], [%1], %2, [%3];"
        :: "r"(dst), "r"(src), "r"(bytes), "r"(mb) : "memory");
}
__device__ __forceinline__ void fence_proxy_async_cta() {
    asm volatile("fence.proxy.async.shared::cta;" ::: "memory");
}
__device__ __forceinline__ void cluster_sync_() {
    asm volatile("barrier.cluster.arrive.aligned;" ::: "memory");
    asm volatile("barrier.cluster.wait.aligned;" ::: "memory");
}

// ---- mma.sync m16n8k16 bf16 (baseline PTX, works on sm_103) ----
#define MMA16816(C, A0, A1, A2, A3, B0, B1)                                    \
    asm volatile(                                                              \
        "mma.sync.aligned.m16n8k16.row.col.f32.bf16.bf16.f32 "                 \
        "{%0,%1,%2,%3}, {%4,%5,%6,%7}, {%8,%9}, {%0,%1,%2,%3};"                \
        : "+f"((C)[0]), "+f"((C)[1]), "+f"((C)[2]), "+f"((C)[3])               \
        : "r"(A0), "r"(A1), "r"(A2), "r"(A3), "r"(B0), "r"(B1))

#define LDS128(R0, R1, R2, R3, ADDR)                                           \
    asm volatile("ld.shared.v4.u32 {%0,%1,%2,%3}, [%4];"                       \
        : "=r"(R0), "=r"(R1), "=r"(R2), "=r"(R3) : "r"(ADDR))

// pack two consecutive-k weight values as bf16x2 (hi or lo split part)
__device__ __forceinline__ unsigned packw(float a, float b, bool useLo) {
    __nv_bfloat16 ah = __float2bfloat16(a);
    __nv_bfloat16 bh = __float2bfloat16(b);
    if (useLo) {
        ah = __float2bfloat16(a - __bfloat162float(ah));
        bh = __float2bfloat16(b - __bfloat162float(bh));
    }
    return (unsigned)__bfloat16_as_ushort(ah)
         | ((unsigned)__bfloat16_as_ushort(bh) << 16);
}

// byte offset (within a B buffer) of the bf16 for (kblock, n, gl)
// where k = kblock*64 + gl
__device__ __forceinline__ unsigned bidx_byte(int rb, int n, int gl) {
    int t0x  = (gl >> 1) & 3;
    int half = (gl >> 3) & 1;
    int ksl  = (gl >> 4) & 3;
    int jlo  = ksl * 2 + half;
    int idx  = (jlo >> 2) * 128 + n * 16 + t0x * 4 + (jlo & 3);
    return (unsigned)(rb * 1024 + idx * 4 + (gl & 1) * 2);
}

__global__ void __launch_bounds__(NTHR, 1)
rnn_kernel(const float* __restrict__ input, const float* __restrict__ Win,
           const float* __restrict__ bin,   const float* __restrict__ Whid,
           const float* __restrict__ bhid,  float* __restrict__ out)
{
    extern __shared__ char sm[];
    const unsigned smemBase = (unsigned)__cvta_generic_to_shared(sm);
    const unsigned mbF = smemBase + MB_OFF;   // full0 @+0, full1 @+8

    const int tid  = threadIdx.x;
    const int lane = tid & 31;
    const int w    = tid >> 5;
    const int gid  = lane >> 2;      // mma group id (row / n col)
    const int t0   = lane & 3;       // thread-in-group
    const int bx   = blockIdx.x;
    const int rank = bx & (CLUSTER - 1);
    const int cl   = bx >> 3;
    const int b0   = cl * 4;
    const int g0   = rank * 64;

    const int  gRow  = (w & 3) * 16 + gid;   // local g row of this thread's tile
    const bool loHalf = (w >= 4);            // warps 4-7: Wlo rows

    // ---- A fragments in registers: 40 k-steps x 4 regs (static indices) ----
    unsigned wf[160];
    #pragma unroll
    for (int ks = 0; ks < 40; ++ks) {
        int k0 = ks * 16 + 2 * t0;
        int ga = g0 + gRow, gb = g0 + gRow + 8;
        #define WVAL(G, K) (ALPHA * (((K) < HDIM) ? Whid[(G) * HDIM + (K)]     \
                                                  : Win[(G) * DDIM + ((K) - HDIM)]))
        wf[ks * 4 + 0] = packw(WVAL(ga, k0),     WVAL(ga, k0 + 1), loHalf);
        wf[ks * 4 + 1] = packw(WVAL(gb, k0),     WVAL(gb, k0 + 1), loHalf);
        wf[ks * 4 + 2] = packw(WVAL(ga, k0 + 8), WVAL(ga, k0 + 9), loHalf);
        wf[ks * 4 + 3] = packw(WVAL(gb, k0 + 8), WVAL(gb, k0 + 9), loHalf);
    }

    // ---- zero both B buffers (fr(0) = 0), then stage x(0) into buf0 ----
    for (int i = tid; i < (2 * BBUF_BYTES) / 16; i += NTHR)
        ((float4*)sm)[i] = make_float4(0.f, 0.f, 0.f, 0.f);
    __syncthreads();
    if (tid >= 128) {
        int d = tid - 128;
        int rb = 8 + (d >> 6), gl = d & 63;
        #pragma unroll
        for (int b = 0; b < 4; ++b) {
            float xv = input[(size_t)(b0 + b) * DDIM + d];
            __nv_bfloat16 hi = __float2bfloat16(xv);
            __nv_bfloat16 lo = __float2bfloat16(xv - __bfloat162float(hi));
            *(unsigned short*)(sm + bidx_byte(rb, b, gl))     = __bfloat16_as_ushort(hi);
            *(unsigned short*)(sm + bidx_byte(rb, b + 4, gl)) = __bfloat16_as_ushort(lo);
        }
    }
    if (tid == 0) {
        mbar_init(mbF + 0, 1); mbar_arrive_expect_tx(mbF + 0, TX_BYTES);
        mbar_init(mbF + 8, 1); mbar_arrive_expect_tx(mbF + 8, TX_BYTES);
    }
    __syncthreads();
    cluster_sync_();   // mbars live before any peer bulk-copy lands

    unsigned peerBase = 0;
    if (tid < 7) {
        unsigned c = (unsigned)tid + ((tid >= rank) ? 1u : 0u);
        peerBase = mapa_u32(smemBase, c);
    }

    // epilogue state (warps 0-3, t0 < 2): rows gRow, gRow+8; batches bb, bb+1
    const int bb = t0 * 2;
    float breg0 = 0.f, breg1 = 0.f;
    float v00 = 0.f, v01 = 0.f, v10 = 0.f, v11 = 0.f;
    if (w < 4 && t0 < 2) {
        breg0 = ALPHA * (bhid[g0 + gRow]     + bin[g0 + gRow]);
        breg1 = ALPHA * (bhid[g0 + gRow + 8] + bin[g0 + gRow + 8]);
    }

    const unsigned bLane = (unsigned)((gid * 16 + t0 * 4) * 4);   // n*16+t0*4 u32

    int ph0 = 0, ph1 = 0, cur = 0;
    for (int t = 0; t < T_STEPS; ++t) {
        // x(t+1) prefetch (warps 4-7) — independent of peers, before the wait
        float xv[4] = {0.f, 0.f, 0.f, 0.f};
        if (w >= 4 && t + 1 < T_STEPS) {
            int d = tid - 128;
            #pragma unroll
            for (int b = 0; b < 4; ++b)
                xv[b] = input[((size_t)(t + 1) * BATCH + b0 + b) * DDIM + d];
        }

        if (t > 0) {
            unsigned mb = mbF + (unsigned)(cur * 8);
            mbar_wait_parity(mb, (unsigned)(cur ? ph1 : ph0));
            if (cur) ph1 ^= 1; else ph0 ^= 1;
            if (tid == 0) mbar_arrive_expect_tx(mb, TX_BYTES);
        }

        // ---- tensor GEMM: 20 conflict-free LDS.128 + 40 HMMA (2 chains) ----
        float c0[4] = {0.f, 0.f, 0.f, 0.f};
        float c1[4] = {0.f, 0.f, 0.f, 0.f};
        const unsigned bBase = smemBase + (unsigned)(cur * BBUF_BYTES) + bLane;
        #pragma unroll
        for (int rb = 0; rb < 10; ++rb) {
            #pragma unroll
            for (int jq = 0; jq < 2; ++jq) {
                unsigned q0, q1, q2, q3;
                LDS128(q0, q1, q2, q3, bBase + (unsigned)(rb * 1024 + jq * 512));
                const int ks = rb * 4 + jq * 2;
                MMA16816(c0, wf[ks * 4 + 0], wf[ks * 4 + 1],
                             wf[ks * 4 + 2], wf[ks * 4 + 3], q0, q1);
                MMA16816(c1, wf[ks * 4 + 4], wf[ks * 4 + 5],
                             wf[ks * 4 + 6], wf[ks * 4 + 7], q2, q3);
            }
        }
        float d0 = c0[0] + c1[0], d1 = c0[1] + c1[1];
        float d2 = c0[2] + c1[2], d3 = c0[3] + c1[3];

        // fold hi/lo activation columns: cols b and b+4 (lanes t0 ^ 2)
        float s0 = d0 + __shfl_xor_sync(0xFFFFFFFFu, d0, 2);
        float s1 = d1 + __shfl_xor_sync(0xFFFFFFFFu, d1, 2);
        float s2 = d2 + __shfl_xor_sync(0xFFFFFFFFu, d2, 2);
        float s3 = d3 + __shfl_xor_sync(0xFFFFFFFFu, d3, 2);

        const int nxt = cur ^ 1;
        char* bn = sm + nxt * BBUF_BYTES;

        if (w >= 4) {
            // Wlo-row partials -> scratch[g][b]
            if (t0 < 2) {
                *(float2*)(sm + SCR_OFF + (gRow * 4 + bb) * 4)       = make_float2(s0, s1);
                *(float2*)(sm + SCR_OFF + ((gRow + 8) * 4 + bb) * 4) = make_float2(s2, s3);
            }
            // stage x(t+1) into next buffer (kblocks 8,9)
            if (t + 1 < T_STEPS) {
                int d = tid - 128;
                int rb = 8 + (d >> 6), gl = d & 63;
                #pragma unroll
                for (int b = 0; b < 4; ++b) {
                    __nv_bfloat16 hi = __float2bfloat16(xv[b]);
                    __nv_bfloat16 lo = __float2bfloat16(xv[b] - __bfloat162float(hi));
                    *(unsigned short*)(bn + bidx_byte(rb, b, gl))     = __bfloat16_as_ushort(hi);
                    *(unsigned short*)(bn + bidx_byte(rb, b + 4, gl)) = __bfloat16_as_ushort(lo);
                }
            }
        }
        __syncthreads();   // scratch + x staging visible

        if (w < 4 && t0 < 2) {
            float2 p0 = *(float2*)(sm + SCR_OFF + (gRow * 4 + bb) * 4);
            float2 p1 = *(float2*)(sm + SCR_OFF + ((gRow + 8) * 4 + bb) * 4);
            v00 = (1.0f - ALPHA) * v00 + (s0 + p0.x + breg0);
            v01 = (1.0f - ALPHA) * v01 + (s1 + p0.y + breg0);
            v10 = (1.0f - ALPHA) * v10 + (s2 + p1.x + breg1);
            v11 = (1.0f - ALPHA) * v11 + (s3 + p1.y + breg1);
            float f00 = fmaxf(v00, 0.f), f01 = fmaxf(v01, 0.f);
            float f10 = fmaxf(v10, 0.f), f11 = fmaxf(v11, 0.f);

            size_t ob = ((size_t)t * BATCH + b0 + bb) * HDIM + g0;
            out[ob + gRow]            = f00;
            out[ob + HDIM + gRow]     = f01;
            out[ob + gRow + 8]        = f10;
            out[ob + HDIM + gRow + 8] = f11;

            if (t + 1 < T_STEPS) {
                // stage own fr slice into next buffer's kblock `rank`
                float fv[4] = {f00, f01, f10, f11};
                int   gv[4] = {gRow, gRow, gRow + 8, gRow + 8};
                int   bv[4] = {bb, bb + 1, bb, bb + 1};
                #pragma unroll
                for (int i = 0; i < 4; ++i) {
                    __nv_bfloat16 hi = __float2bfloat16(fv[i]);
                    __nv_bfloat16 lo = __float2bfloat16(fv[i] - __bfloat162float(hi));
                    *(unsigned short*)(bn + bidx_byte(rank, bv[i], gv[i]))
                        = __bfloat16_as_ushort(hi);
                    *(unsigned short*)(bn + bidx_byte(rank, bv[i] + 4, gv[i]))
                        = __bfloat16_as_ushort(lo);
                }
            }
        }
        __syncthreads();   // own kblock complete before push

        if (t + 1 < T_STEPS && tid < 7) {
            fence_proxy_async_cta();
            unsigned off = (unsigned)(nxt * BBUF_BYTES + rank * 1024);
            bulk_dsmem(peerBase + off, smemBase + off, 1024,
                       peerBase + (unsigned)(MB_OFF + nxt * 8));
        }
        cur ^= 1;
    }
}

extern "C" void kernel_launch(void* const* d_in, const int* in_sizes, int n_in,
                              void* d_out, int out_size)
{
    const float* input = (const float*)d_in[0];
    const float* Win   = (const float*)d_in[1];
    const float* bin   = (const float*)d_in[2];
    const float* Whid  = (const float*)d_in[3];
    const float* bhid  = (const float*)d_in[4];
    float* out = (float*)d_out;

    cudaFuncSetAttribute(rnn_kernel,
                         cudaFuncAttributeMaxDynamicSharedMemorySize, SMEM_BYTES);

    cudaLaunchConfig_t cfg = {};
    cfg.gridDim  = dim3(16 * CLUSTER, 1, 1);
    cfg.blockDim = dim3(NTHR, 1, 1);
    cfg.dynamicSmemBytes = SMEM_BYTES;
    cfg.stream = 0;

    cudaLaunchAttribute attr[1];
    attr[0].id = cudaLaunchAttributeClusterDimension;
    attr[0].val.clusterDim.x = CLUSTER;
    attr[0].val.clusterDim.y = 1;
    attr[0].val.clusterDim.z = 1;
    cfg.attrs = attr;
    cfg.numAttrs = 1;

    cudaLaunchKernelEx(&cfg, rnn_kernel, input, Win, bin, Whid, bhid, out);
}